// round 1
// baseline (speedup 1.0000x reference)
#include <cuda_runtime.h>
#include <cstdint>
#include <cstddef>

// Problem constants
#define B_   16
#define CIN  512
#define HW   4096
#define CP   256
#define G_   8
#define EPSG 1e-5f

// GEMM tiling
#define AS_LD 36     // A smem row stride (32 + 4 pad) -> conflict-free frag reads
#define BS_LD 136    // B smem row stride (128 + 8 pad)
#define SMEM_WORDS (128*AS_LD + 32*BS_LD)   // 4608 + 4352 = 8960 u32 = 35840 B

// ---------------- device scratch (static, allocation-free) ----------------
__device__ float g_Wcomb[CIN*CIN];                      // 512x512 fused Wz*Wt
__device__ float g_u[(size_t)B_*CIN*HW];                // 134 MB intermediate u = Wcomb@x
__device__ float g_attp[B_*G_*32];                      // per-spatial-tile att partials
__device__ float g_sump[B_*G_*32];
__device__ float g_sumsqp[B_*G_*32];
__device__ float g_scale[B_*CIN];
__device__ float g_bias[B_*CIN];

// ---------------- helpers ----------------
__device__ __forceinline__ unsigned f2tf(float f) {
    unsigned u;
    asm("cvt.rna.tf32.f32 %0, %1;" : "=r"(u) : "f"(f));
    return u;
}

__device__ __forceinline__ void mma8(float* c, const unsigned* a, const unsigned* b) {
    asm volatile(
        "mma.sync.aligned.m16n8k8.row.col.f32.tf32.tf32.f32 "
        "{%0,%1,%2,%3}, {%4,%5,%6,%7}, {%8,%9}, {%0,%1,%2,%3};\n"
        : "+f"(c[0]), "+f"(c[1]), "+f"(c[2]), "+f"(c[3])
        : "r"(a[0]), "r"(a[1]), "r"(a[2]), "r"(a[3]), "r"(b[0]), "r"(b[1]));
}

__device__ __forceinline__ float wred(float v) {
#pragma unroll
    for (int o = 16; o; o >>= 1) v += __shfl_down_sync(0xffffffffu, v, o);
    return v;
}

// ---------------- K1: Wcomb[g*64+o, i] = sum_c Wz[g,o,c] * Wt[g*32+c, i] ----------------
__global__ void k_prep(const float* __restrict__ Wt, const float* __restrict__ Wz) {
    int r = blockIdx.x;          // 0..511
    int g = r >> 6, o = r & 63;
    __shared__ float wz[32];
    if (threadIdx.x < 32) wz[threadIdx.x] = Wz[(size_t)(g*64 + o)*32 + threadIdx.x];
    __syncthreads();
    for (int i = threadIdx.x; i < CIN; i += blockDim.x) {
        float a = 0.f;
#pragma unroll 8
        for (int c = 0; c < 32; c++)
            a += wz[c] * Wt[(size_t)(g*32 + c)*CIN + i];
        g_Wcomb[(size_t)r*CIN + i] = a;
    }
}

// ---------------- K2: att partials.  C(128xNt) = [Wp_chunk; Wg_chunk](128x512) @ X(512x128) ----------------
__global__ void __launch_bounds__(256, 1)
k_att(const float* __restrict__ x, const float* __restrict__ Wp, const float* __restrict__ Wg) {
    extern __shared__ unsigned sm[];
    unsigned* As = sm;                  // [128][AS_LD]
    unsigned* Bs = sm + 128*AS_LD;      // [32][BS_LD]
    __shared__ float sred[8];

    const int tid  = threadIdx.x;
    const int lane = tid & 31, warp = tid >> 5;
    const int wm = warp >> 2, wn = warp & 3;        // warp grid 2x4 on 128x128
    const int b = blockIdx.z, chunk = blockIdx.y, stile = blockIdx.x;
    const int c0 = chunk * 64;
    const int scol0 = stile * 128;

    const int la_m = tid >> 3, la_k = (tid & 7) * 4;   // A loader: rows +{0,32,64,96}
    const int lb_k = tid >> 5, lb_n = (tid & 31) * 4;  // B loader: k rows +{0,8,16,24}

    const float* ab[4];
    const float* bb[4];
#pragma unroll
    for (int p = 0; p < 4; p++) {
        int row = la_m + p*32;
        ab[p] = (row < 64 ? Wp + (size_t)(c0 + row)*CIN
                          : Wg + (size_t)(c0 + row - 64)*CIN) + la_k;
        bb[p] = x + ((size_t)b*CIN + lb_k + p*8)*HW + scol0 + lb_n;
    }

    float acc[4][4][4];
#pragma unroll
    for (int mt = 0; mt < 4; mt++)
#pragma unroll
        for (int nt = 0; nt < 4; nt++)
#pragma unroll
            for (int i = 0; i < 4; i++) acc[mt][nt][i] = 0.f;

    float4 pa[4], pb[4];
#pragma unroll
    for (int p = 0; p < 4; p++) { pa[p] = *(const float4*)ab[p]; pb[p] = *(const float4*)bb[p]; }

    auto do_sts = [&]() {
#pragma unroll
        for (int p = 0; p < 4; p++) {
            uint4 t;
            t.x = f2tf(pa[p].x); t.y = f2tf(pa[p].y); t.z = f2tf(pa[p].z); t.w = f2tf(pa[p].w);
            *(uint4*)&As[(la_m + p*32)*AS_LD + la_k] = t;
            uint4 s;
            s.x = f2tf(pb[p].x); s.y = f2tf(pb[p].y); s.z = f2tf(pb[p].z); s.w = f2tf(pb[p].w);
            *(uint4*)&Bs[(lb_k + p*8)*BS_LD + lb_n] = s;
        }
    };
    do_sts();

    const int mbase = wm * 64, nbase = wn * 32;

    for (int kb = 0; kb < CIN; kb += 32) {
        __syncthreads();
        if (kb + 32 < CIN) {
#pragma unroll
            for (int p = 0; p < 4; p++) {
                pa[p] = *(const float4*)(ab[p] + kb + 32);
                pb[p] = *(const float4*)(bb[p] + (size_t)(kb + 32)*HW);
            }
        }
#pragma unroll
        for (int ks = 0; ks < 4; ks++) {
            unsigned af[4][4], bf[4][2];
            const int kk = ks*8 + (lane & 3);
#pragma unroll
            for (int mt = 0; mt < 4; mt++) {
                int r = mbase + mt*16 + (lane >> 2);
                af[mt][0] = As[r*AS_LD + kk];
                af[mt][1] = As[(r + 8)*AS_LD + kk];
                af[mt][2] = As[r*AS_LD + kk + 4];
                af[mt][3] = As[(r + 8)*AS_LD + kk + 4];
            }
#pragma unroll
            for (int nt = 0; nt < 4; nt++) {
                int cc = nbase + nt*8 + (lane >> 2);
                bf[nt][0] = Bs[kk*BS_LD + cc];
                bf[nt][1] = Bs[(kk + 4)*BS_LD + cc];
            }
#pragma unroll
            for (int mt = 0; mt < 4; mt++)
#pragma unroll
                for (int nt = 0; nt < 4; nt++)
                    mma8(acc[mt][nt], af[mt], bf[nt]);
        }
        __syncthreads();
        if (kb + 32 < CIN) do_sts();
    }

    // Epilogue: P rows live in wm=0 warps, G rows (same channels) in wm=1.
    // wm=1 dumps its tile to smem (aliases As/Bs, safe after final sync), then wm=0 forms p*g.
    float* Gs = (float*)sm;  // [64][132]
    if (wm == 1) {
#pragma unroll
        for (int mt = 0; mt < 4; mt++)
#pragma unroll
            for (int nt = 0; nt < 4; nt++)
#pragma unroll
                for (int i2 = 0; i2 < 2; i2++) {
                    int r  = mt*16 + (lane >> 2) + i2*8;      // = channel_local
                    int cl = nbase + nt*8 + (lane & 3)*2;
                    Gs[r*132 + cl]     = acc[mt][nt][i2*2];
                    Gs[r*132 + cl + 1] = acc[mt][nt][i2*2 + 1];
                }
    }
    __syncthreads();
    if (wm == 0) {
        float pg0 = 0.f, pg1 = 0.f;
#pragma unroll
        for (int mt = 0; mt < 4; mt++) {
            float local = 0.f;
#pragma unroll
            for (int nt = 0; nt < 4; nt++)
#pragma unroll
                for (int i2 = 0; i2 < 2; i2++) {
                    int r  = mt*16 + (lane >> 2) + i2*8;
                    int cl = nbase + nt*8 + (lane & 3)*2;
                    local += acc[mt][nt][i2*2]     * Gs[r*132 + cl]
                           + acc[mt][nt][i2*2 + 1] * Gs[r*132 + cl + 1];
                }
            if (mt < 2) pg0 += local; else pg1 += local;   // channel<32 vs >=32 => two CGNL groups
        }
        pg0 = wred(pg0); pg1 = wred(pg1);
        if (lane == 0) { sred[wn] = pg0; sred[4 + wn] = pg1; }
    }
    __syncthreads();
    if (tid == 0) {
        g_attp[((b*G_ + chunk*2 + 0)*32) + stile] = sred[0] + sred[1] + sred[2] + sred[3];
        g_attp[((b*G_ + chunk*2 + 1)*32) + stile] = sred[4] + sred[5] + sred[6] + sred[7];
    }
}

// ---------------- K3: u = Wcomb @ x (tile) + per-(b,group) sum/sumsq partials ----------------
__global__ void __launch_bounds__(256, 1)
k_u(const float* __restrict__ x) {
    extern __shared__ unsigned sm[];
    unsigned* As = sm;
    unsigned* Bs = sm + 128*AS_LD;
    __shared__ float r2[16];

    const int tid  = threadIdx.x;
    const int lane = tid & 31, warp = tid >> 5;
    const int wm = warp >> 2, wn = warp & 3;
    const int b = blockIdx.z, rowtile = blockIdx.y, stile = blockIdx.x;
    const int rowbase = rowtile * 128;
    const int scol0 = stile * 128;

    const int la_m = tid >> 3, la_k = (tid & 7) * 4;
    const int lb_k = tid >> 5, lb_n = (tid & 31) * 4;

    const float* ab[4];
    const float* bb[4];
#pragma unroll
    for (int p = 0; p < 4; p++) {
        ab[p] = g_Wcomb + (size_t)(rowbase + la_m + p*32)*CIN + la_k;
        bb[p] = x + ((size_t)b*CIN + lb_k + p*8)*HW + scol0 + lb_n;
    }

    float acc[4][4][4];
#pragma unroll
    for (int mt = 0; mt < 4; mt++)
#pragma unroll
        for (int nt = 0; nt < 4; nt++)
#pragma unroll
            for (int i = 0; i < 4; i++) acc[mt][nt][i] = 0.f;

    float4 pa[4], pb[4];
#pragma unroll
    for (int p = 0; p < 4; p++) { pa[p] = *(const float4*)ab[p]; pb[p] = *(const float4*)bb[p]; }

    auto do_sts = [&]() {
#pragma unroll
        for (int p = 0; p < 4; p++) {
            uint4 t;
            t.x = f2tf(pa[p].x); t.y = f2tf(pa[p].y); t.z = f2tf(pa[p].z); t.w = f2tf(pa[p].w);
            *(uint4*)&As[(la_m + p*32)*AS_LD + la_k] = t;
            uint4 s;
            s.x = f2tf(pb[p].x); s.y = f2tf(pb[p].y); s.z = f2tf(pb[p].z); s.w = f2tf(pb[p].w);
            *(uint4*)&Bs[(lb_k + p*8)*BS_LD + lb_n] = s;
        }
    };
    do_sts();

    const int mbase = wm * 64, nbase = wn * 32;

    for (int kb = 0; kb < CIN; kb += 32) {
        __syncthreads();
        if (kb + 32 < CIN) {
#pragma unroll
            for (int p = 0; p < 4; p++) {
                pa[p] = *(const float4*)(ab[p] + kb + 32);
                pb[p] = *(const float4*)(bb[p] + (size_t)(kb + 32)*HW);
            }
        }
#pragma unroll
        for (int ks = 0; ks < 4; ks++) {
            unsigned af[4][4], bf[4][2];
            const int kk = ks*8 + (lane & 3);
#pragma unroll
            for (int mt = 0; mt < 4; mt++) {
                int r = mbase + mt*16 + (lane >> 2);
                af[mt][0] = As[r*AS_LD + kk];
                af[mt][1] = As[(r + 8)*AS_LD + kk];
                af[mt][2] = As[r*AS_LD + kk + 4];
                af[mt][3] = As[(r + 8)*AS_LD + kk + 4];
            }
#pragma unroll
            for (int nt = 0; nt < 4; nt++) {
                int cc = nbase + nt*8 + (lane >> 2);
                bf[nt][0] = Bs[kk*BS_LD + cc];
                bf[nt][1] = Bs[(kk + 4)*BS_LD + cc];
            }
#pragma unroll
            for (int mt = 0; mt < 4; mt++)
#pragma unroll
                for (int nt = 0; nt < 4; nt++)
                    mma8(acc[mt][nt], af[mt], bf[nt]);
        }
        __syncthreads();
        if (kb + 32 < CIN) do_sts();
    }

    // Epilogue: store u, accumulate group stats (each warp touches exactly one GN group)
    float s = 0.f, s2 = 0.f;
    size_t ubase = ((size_t)b*CIN + rowbase)*HW + scol0;
#pragma unroll
    for (int mt = 0; mt < 4; mt++)
#pragma unroll
        for (int nt = 0; nt < 4; nt++)
#pragma unroll
            for (int i2 = 0; i2 < 2; i2++) {
                int r  = mbase + mt*16 + (lane >> 2) + i2*8;
                int cl = nbase + nt*8 + (lane & 3)*2;
                float v0 = acc[mt][nt][i2*2], v1 = acc[mt][nt][i2*2 + 1];
                float2 st; st.x = v0; st.y = v1;
                *(float2*)&g_u[ubase + (size_t)r*HW + cl] = st;
                s  += v0 + v1;
                s2 += v0*v0 + v1*v1;
            }
    s = wred(s); s2 = wred(s2);
    if (lane == 0) { r2[wm*8 + wn] = s; r2[wm*8 + 4 + wn] = s2; }
    __syncthreads();
    if (tid < 2) {
        int g = rowtile*2 + tid;
        float ss = r2[tid*8 + 0] + r2[tid*8 + 1] + r2[tid*8 + 2] + r2[tid*8 + 3];
        float qq = r2[tid*8 + 4] + r2[tid*8 + 5] + r2[tid*8 + 6] + r2[tid*8 + 7];
        g_sump[((b*G_ + g)*32) + stile]   = ss;
        g_sumsqp[((b*G_ + g)*32) + stile] = qq;
    }
}

// ---------------- K4: fold att + GN stats into per-(b,c) scale/bias ----------------
__global__ void k_stats(const float* __restrict__ gamma, const float* __restrict__ beta) {
    int b = blockIdx.x, c = threadIdx.x;
    __shared__ float sS[8], sMu[8];
    if (c < 8) {
        float att = 0.f, sm = 0.f, sq = 0.f;
#pragma unroll
        for (int t = 0; t < 32; t++) {
            att += g_attp[(b*G_ + c)*32 + t];
            sm  += g_sump[(b*G_ + c)*32 + t];
            sq  += g_sumsqp[(b*G_ + c)*32 + t];
        }
        const float n = 64.0f * 4096.0f;
        float mu  = sm / n;
        float var = fmaxf(sq / n - mu*mu, 0.f);
        float rstd = rsqrtf(att*att*var + EPSG);   // var_z = att^2 * var_u
        sS[c]  = att * rstd;
        sMu[c] = mu;
    }
    __syncthreads();
    int g = c >> 6;
    float S = sS[g], mu = sMu[g];
    g_scale[b*CIN + c] = S * gamma[c];
    g_bias[b*CIN + c]  = beta[c] - S * mu * gamma[c];
}

// ---------------- K5: out = scale*u + bias + x ----------------
__global__ void k_final(const float* __restrict__ x, float* __restrict__ out) {
    size_t i = (size_t)blockIdx.x * blockDim.x + threadIdx.x;   // float4 index
    size_t e = i << 2;
    int b = (int)(e >> 21);            // 512*4096 = 2^21
    int c = (int)((e >> 12) & 511);    // HW = 2^12
    float sc = g_scale[b*CIN + c];
    float bi = g_bias[b*CIN + c];
    float4 u4 = ((const float4*)g_u)[i];
    float4 x4 = ((const float4*)x)[i];
    float4 o;
    o.x = fmaf(sc, u4.x, bi + x4.x);
    o.y = fmaf(sc, u4.y, bi + x4.y);
    o.z = fmaf(sc, u4.z, bi + x4.z);
    o.w = fmaf(sc, u4.w, bi + x4.w);
    ((float4*)out)[i] = o;
}

// ---------------- launch ----------------
extern "C" void kernel_launch(void* const* d_in, const int* in_sizes, int n_in,
                              void* d_out, int out_size) {
    const float* x     = (const float*)d_in[0];
    const float* Wt    = (const float*)d_in[1];
    const float* Wp    = (const float*)d_in[2];
    const float* Wg    = (const float*)d_in[3];
    const float* Wz    = (const float*)d_in[4];
    const float* gamma = (const float*)d_in[5];
    const float* beta  = (const float*)d_in[6];
    float* out = (float*)d_out;

    const size_t smem = SMEM_WORDS * sizeof(unsigned);  // 35840 B

    k_prep<<<512, 128>>>(Wt, Wz);
    k_att<<<dim3(32, 4, B_), 256, smem>>>(x, Wp, Wg);
    k_u<<<dim3(32, 4, B_), 256, smem>>>(x);
    k_stats<<<B_, CIN>>>(gamma, beta);
    k_final<<<32768, 256>>>(x, out);
}

// round 3
// speedup vs baseline: 1.4038x; 1.4038x over previous
#include <cuda_runtime.h>
#include <cuda_fp16.h>
#include <cstdint>
#include <cstddef>

// Problem constants
#define B_   16
#define CIN  512
#define HW   4096
#define G_   8
#define EPSG 1e-5f

// GEMM tiling: CTA tile 128(M) x 128(N), K-stage 32 (= 16 packed-half2 words)
#define AS_LD 20     // A smem row stride in words (16 + 4 pad)
#define BS_LD 136    // B smem row stride in words (128 + 8 pad)
#define GEMM_WORDS (128*AS_LD + 16*BS_LD)       // 2560 + 2176 = 4736 words
#define SMEM_BYTES 33792                         // max(GEMM 18944, att dump 64*132*4)

// ---------------- device scratch (static, allocation-free) ----------------
__device__ float  g_Wcomb[CIN*CIN];
__device__ __half g_u[(size_t)B_*CIN*HW];        // 67 MB fp16 intermediate
__device__ float  g_attp[B_*G_*32];
__device__ float  g_sump[B_*G_*32];
__device__ float  g_sumsqp[B_*G_*32];
__device__ float  g_scale[B_*CIN];
__device__ float  g_bias[B_*CIN];

// ---------------- helpers ----------------
__device__ __forceinline__ unsigned pk(float lo, float hi) {
    __half2 h = __floats2half2_rn(lo, hi);       // .x = lo (even k), .y = hi (odd k)
    return *(unsigned*)&h;
}

__device__ __forceinline__ void mma16(float* c, const unsigned* a, const unsigned* b) {
    asm volatile(
        "mma.sync.aligned.m16n8k16.row.col.f32.f16.f16.f32 "
        "{%0,%1,%2,%3}, {%4,%5,%6,%7}, {%8,%9}, {%0,%1,%2,%3};\n"
        : "+f"(c[0]), "+f"(c[1]), "+f"(c[2]), "+f"(c[3])
        : "r"(a[0]), "r"(a[1]), "r"(a[2]), "r"(a[3]), "r"(b[0]), "r"(b[1]));
}

__device__ __forceinline__ float wred(float v) {
#pragma unroll
    for (int o = 16; o; o >>= 1) v += __shfl_down_sync(0xffffffffu, v, o);
    return v;
}

// ---------------- K1: Wcomb[g*64+o, i] = sum_c Wz[g,o,c] * Wt[g*32+c, i] ----------------
__global__ void k_prep(const float* __restrict__ Wt, const float* __restrict__ Wz) {
    int r = blockIdx.x;          // 0..511
    int g = r >> 6, o = r & 63;
    __shared__ float wz[32];
    if (threadIdx.x < 32) wz[threadIdx.x] = Wz[(size_t)(g*64 + o)*32 + threadIdx.x];
    __syncthreads();
    for (int i = threadIdx.x; i < CIN; i += blockDim.x) {
        float a = 0.f;
#pragma unroll 8
        for (int c = 0; c < 32; c++)
            a += wz[c] * Wt[(size_t)(g*32 + c)*CIN + i];
        g_Wcomb[(size_t)r*CIN + i] = a;
    }
}

// ---------------- K2: att partials.  C(128x128) = [Wp_chunk; Wg_chunk](128x512) @ X(512x128) ----------------
__global__ void __launch_bounds__(256, 1)
k_att(const float* __restrict__ x, const float* __restrict__ Wp, const float* __restrict__ Wg) {
    extern __shared__ unsigned sm[];
    unsigned* As = sm;                  // [128][AS_LD] packed half2 words
    unsigned* Bs = sm + 128*AS_LD;      // [16][BS_LD]  packed half2 words
    __shared__ float sred[8];

    const int tid  = threadIdx.x;
    const int lane = tid & 31, warp = tid >> 5;
    const int wm = warp >> 2, wn = warp & 3;        // warp grid 2x4 on 128x128
    const int b = blockIdx.z, chunk = blockIdx.y, stile = blockIdx.x;
    const int c0 = chunk * 64;
    const int scol0 = stile * 128;

    const int la_m = tid >> 3, la_k4 = tid & 7;     // A: float4 index within 32-k stage
    const int lb_k2 = tid >> 5, lb_n = (tid & 31) * 4;  // B: k2 row + n chunk

    const float* ab[4];
    const float* bb0[2];
#pragma unroll
    for (int p = 0; p < 4; p++) {
        int row = la_m + p*32;
        ab[p] = (row < 64 ? Wp + (size_t)(c0 + row)*CIN
                          : Wg + (size_t)(c0 + row - 64)*CIN) + la_k4*4;
    }
#pragma unroll
    for (int p = 0; p < 2; p++)
        bb0[p] = x + ((size_t)b*CIN + 2*(lb_k2 + p*8))*HW + scol0 + lb_n;

    float acc[4][4][4];
#pragma unroll
    for (int mt = 0; mt < 4; mt++)
#pragma unroll
        for (int nt = 0; nt < 4; nt++)
#pragma unroll
            for (int i = 0; i < 4; i++) acc[mt][nt][i] = 0.f;

    float4 pa[4], pb0[2], pb1[2];
#pragma unroll
    for (int p = 0; p < 4; p++) pa[p] = *(const float4*)ab[p];
#pragma unroll
    for (int p = 0; p < 2; p++) {
        pb0[p] = *(const float4*)bb0[p];
        pb1[p] = *(const float4*)(bb0[p] + HW);
    }

    auto do_sts = [&]() {
#pragma unroll
        for (int p = 0; p < 4; p++) {
            uint2 t;
            t.x = pk(pa[p].x, pa[p].y);
            t.y = pk(pa[p].z, pa[p].w);
            *(uint2*)&As[(la_m + p*32)*AS_LD + la_k4*2] = t;
        }
#pragma unroll
        for (int p = 0; p < 2; p++) {
            uint4 t;
            t.x = pk(pb0[p].x, pb1[p].x);
            t.y = pk(pb0[p].y, pb1[p].y);
            t.z = pk(pb0[p].z, pb1[p].z);
            t.w = pk(pb0[p].w, pb1[p].w);
            *(uint4*)&Bs[(lb_k2 + p*8)*BS_LD + lb_n] = t;
        }
    };
    do_sts();

    const int mbase = wm * 64, nbase = wn * 32;

    for (int kb = 0; kb < CIN; kb += 32) {
        __syncthreads();
        if (kb + 32 < CIN) {
#pragma unroll
            for (int p = 0; p < 4; p++) pa[p] = *(const float4*)(ab[p] + kb + 32);
#pragma unroll
            for (int p = 0; p < 2; p++) {
                pb0[p] = *(const float4*)(bb0[p] + (size_t)(kb + 32)*HW);
                pb1[p] = *(const float4*)(bb0[p] + (size_t)(kb + 33)*HW);
            }
        }
#pragma unroll
        for (int ks = 0; ks < 2; ks++) {
            unsigned af[4][4], bf[4][2];
            const int kk = ks*8 + (lane & 3);
#pragma unroll
            for (int mt = 0; mt < 4; mt++) {
                int r = mbase + mt*16 + (lane >> 2);
                af[mt][0] = As[r*AS_LD + kk];
                af[mt][1] = As[(r + 8)*AS_LD + kk];
                af[mt][2] = As[r*AS_LD + kk + 4];
                af[mt][3] = As[(r + 8)*AS_LD + kk + 4];
            }
#pragma unroll
            for (int nt = 0; nt < 4; nt++) {
                int cc = nbase + nt*8 + (lane >> 2);
                bf[nt][0] = Bs[kk*BS_LD + cc];
                bf[nt][1] = Bs[(kk + 4)*BS_LD + cc];
            }
#pragma unroll
            for (int mt = 0; mt < 4; mt++)
#pragma unroll
                for (int nt = 0; nt < 4; nt++)
                    mma16(acc[mt][nt], af[mt], bf[nt]);
        }
        __syncthreads();
        if (kb + 32 < CIN) do_sts();
    }

    // Epilogue: wm=1 warps hold G rows (same channels as wm=0's P rows); dump, multiply, reduce.
    float* Gs = (float*)sm;  // [64][132]
    if (wm == 1) {
#pragma unroll
        for (int mt = 0; mt < 4; mt++)
#pragma unroll
            for (int nt = 0; nt < 4; nt++)
#pragma unroll
                for (int i2 = 0; i2 < 2; i2++) {
                    int r  = mt*16 + (lane >> 2) + i2*8;
                    int cl = nbase + nt*8 + (lane & 3)*2;
                    Gs[r*132 + cl]     = acc[mt][nt][i2*2];
                    Gs[r*132 + cl + 1] = acc[mt][nt][i2*2 + 1];
                }
    }
    __syncthreads();
    if (wm == 0) {
        float pg0 = 0.f, pg1 = 0.f;
#pragma unroll
        for (int mt = 0; mt < 4; mt++) {
            float local = 0.f;
#pragma unroll
            for (int nt = 0; nt < 4; nt++)
#pragma unroll
                for (int i2 = 0; i2 < 2; i2++) {
                    int r  = mt*16 + (lane >> 2) + i2*8;
                    int cl = nbase + nt*8 + (lane & 3)*2;
                    local += acc[mt][nt][i2*2]     * Gs[r*132 + cl]
                           + acc[mt][nt][i2*2 + 1] * Gs[r*132 + cl + 1];
                }
            if (mt < 2) pg0 += local; else pg1 += local;
        }
        pg0 = wred(pg0); pg1 = wred(pg1);
        if (lane == 0) { sred[wn] = pg0; sred[4 + wn] = pg1; }
    }
    __syncthreads();
    if (tid == 0) {
        g_attp[((b*G_ + chunk*2 + 0)*32) + stile] = sred[0] + sred[1] + sred[2] + sred[3];
        g_attp[((b*G_ + chunk*2 + 1)*32) + stile] = sred[4] + sred[5] + sred[6] + sred[7];
    }
}

// ---------------- K3: u = Wcomb @ x (fp16 store) + per-(b,group) sum/sumsq partials ----------------
__global__ void __launch_bounds__(256, 1)
k_u(const float* __restrict__ x) {
    extern __shared__ unsigned sm[];
    unsigned* As = sm;
    unsigned* Bs = sm + 128*AS_LD;
    __shared__ float r2[16];

    const int tid  = threadIdx.x;
    const int lane = tid & 31, warp = tid >> 5;
    const int wm = warp >> 2, wn = warp & 3;
    const int b = blockIdx.z, rowtile = blockIdx.y, stile = blockIdx.x;
    const int rowbase = rowtile * 128;
    const int scol0 = stile * 128;

    const int la_m = tid >> 3, la_k4 = tid & 7;
    const int lb_k2 = tid >> 5, lb_n = (tid & 31) * 4;

    const float* ab[4];
    const float* bb0[2];
#pragma unroll
    for (int p = 0; p < 4; p++)
        ab[p] = g_Wcomb + (size_t)(rowbase + la_m + p*32)*CIN + la_k4*4;
#pragma unroll
    for (int p = 0; p < 2; p++)
        bb0[p] = x + ((size_t)b*CIN + 2*(lb_k2 + p*8))*HW + scol0 + lb_n;

    float acc[4][4][4];
#pragma unroll
    for (int mt = 0; mt < 4; mt++)
#pragma unroll
        for (int nt = 0; nt < 4; nt++)
#pragma unroll
            for (int i = 0; i < 4; i++) acc[mt][nt][i] = 0.f;

    float4 pa[4], pb0[2], pb1[2];
#pragma unroll
    for (int p = 0; p < 4; p++) pa[p] = *(const float4*)ab[p];
#pragma unroll
    for (int p = 0; p < 2; p++) {
        pb0[p] = *(const float4*)bb0[p];
        pb1[p] = *(const float4*)(bb0[p] + HW);
    }

    auto do_sts = [&]() {
#pragma unroll
        for (int p = 0; p < 4; p++) {
            uint2 t;
            t.x = pk(pa[p].x, pa[p].y);
            t.y = pk(pa[p].z, pa[p].w);
            *(uint2*)&As[(la_m + p*32)*AS_LD + la_k4*2] = t;
        }
#pragma unroll
        for (int p = 0; p < 2; p++) {
            uint4 t;
            t.x = pk(pb0[p].x, pb1[p].x);
            t.y = pk(pb0[p].y, pb1[p].y);
            t.z = pk(pb0[p].z, pb1[p].z);
            t.w = pk(pb0[p].w, pb1[p].w);
            *(uint4*)&Bs[(lb_k2 + p*8)*BS_LD + lb_n] = t;
        }
    };
    do_sts();

    const int mbase = wm * 64, nbase = wn * 32;

    for (int kb = 0; kb < CIN; kb += 32) {
        __syncthreads();
        if (kb + 32 < CIN) {
#pragma unroll
            for (int p = 0; p < 4; p++) pa[p] = *(const float4*)(ab[p] + kb + 32);
#pragma unroll
            for (int p = 0; p < 2; p++) {
                pb0[p] = *(const float4*)(bb0[p] + (size_t)(kb + 32)*HW);
                pb1[p] = *(const float4*)(bb0[p] + (size_t)(kb + 33)*HW);
            }
        }
#pragma unroll
        for (int ks = 0; ks < 2; ks++) {
            unsigned af[4][4], bf[4][2];
            const int kk = ks*8 + (lane & 3);
#pragma unroll
            for (int mt = 0; mt < 4; mt++) {
                int r = mbase + mt*16 + (lane >> 2);
                af[mt][0] = As[r*AS_LD + kk];
                af[mt][1] = As[(r + 8)*AS_LD + kk];
                af[mt][2] = As[r*AS_LD + kk + 4];
                af[mt][3] = As[(r + 8)*AS_LD + kk + 4];
            }
#pragma unroll
            for (int nt = 0; nt < 4; nt++) {
                int cc = nbase + nt*8 + (lane >> 2);
                bf[nt][0] = Bs[kk*BS_LD + cc];
                bf[nt][1] = Bs[(kk + 4)*BS_LD + cc];
            }
#pragma unroll
            for (int mt = 0; mt < 4; mt++)
#pragma unroll
                for (int nt = 0; nt < 4; nt++)
                    mma16(acc[mt][nt], af[mt], bf[nt]);
        }
        __syncthreads();
        if (kb + 32 < CIN) do_sts();
    }

    // Epilogue: store u (fp16) + accumulate group stats
    float s = 0.f, s2 = 0.f;
    size_t ubase = ((size_t)b*CIN + rowbase)*HW + scol0;
#pragma unroll
    for (int mt = 0; mt < 4; mt++)
#pragma unroll
        for (int nt = 0; nt < 4; nt++)
#pragma unroll
            for (int i2 = 0; i2 < 2; i2++) {
                int r  = mbase + mt*16 + (lane >> 2) + i2*8;
                int cl = nbase + nt*8 + (lane & 3)*2;
                float v0 = acc[mt][nt][i2*2], v1 = acc[mt][nt][i2*2 + 1];
                *(__half2*)&g_u[ubase + (size_t)r*HW + cl] = __floats2half2_rn(v0, v1);
                s  += v0 + v1;
                s2 += v0*v0 + v1*v1;
            }
    s = wred(s); s2 = wred(s2);
    if (lane == 0) { r2[wm*8 + wn] = s; r2[wm*8 + 4 + wn] = s2; }
    __syncthreads();
    if (tid < 2) {
        int g = rowtile*2 + tid;
        float ss = r2[tid*8 + 0] + r2[tid*8 + 1] + r2[tid*8 + 2] + r2[tid*8 + 3];
        float qq = r2[tid*8 + 4] + r2[tid*8 + 5] + r2[tid*8 + 6] + r2[tid*8 + 7];
        g_sump[((b*G_ + g)*32) + stile]   = ss;
        g_sumsqp[((b*G_ + g)*32) + stile] = qq;
    }
}

// ---------------- K4: fold att + GN stats into per-(b,c) scale/bias ----------------
__global__ void k_stats(const float* __restrict__ gamma, const float* __restrict__ beta) {
    int b = blockIdx.x, c = threadIdx.x;
    __shared__ float sS[8], sMu[8];
    if (c < 8) {
        float att = 0.f, sm = 0.f, sq = 0.f;
#pragma unroll
        for (int t = 0; t < 32; t++) {
            att += g_attp[(b*G_ + c)*32 + t];
            sm  += g_sump[(b*G_ + c)*32 + t];
            sq  += g_sumsqp[(b*G_ + c)*32 + t];
        }
        const float n = 64.0f * 4096.0f;
        float mu  = sm / n;
        float var = fmaxf(sq / n - mu*mu, 0.f);
        float rstd = rsqrtf(att*att*var + EPSG);   // var_z = att^2 * var_u
        sS[c]  = att * rstd;
        sMu[c] = mu;
    }
    __syncthreads();
    int g = c >> 6;
    float S = sS[g], mu = sMu[g];
    g_scale[b*CIN + c] = S * gamma[c];
    g_bias[b*CIN + c]  = beta[c] - S * mu * gamma[c];
}

// ---------------- K5: out = scale*u + bias + x ----------------
__global__ void k_final(const float* __restrict__ x, float* __restrict__ out) {
    size_t i = (size_t)blockIdx.x * blockDim.x + threadIdx.x;   // float4 index
    size_t e = i << 2;
    int b = (int)(e >> 21);            // 512*4096 = 2^21
    int c = (int)((e >> 12) & 511);    // HW = 2^12
    float sc = g_scale[b*CIN + c];
    float bi = g_bias[b*CIN + c];
    const __half2* up = (const __half2*)g_u;
    float2 u0 = __half22float2(up[2*i]);
    float2 u1 = __half22float2(up[2*i + 1]);
    float4 x4 = ((const float4*)x)[i];
    float4 o;
    o.x = fmaf(sc, u0.x, bi + x4.x);
    o.y = fmaf(sc, u0.y, bi + x4.y);
    o.z = fmaf(sc, u1.x, bi + x4.z);
    o.w = fmaf(sc, u1.y, bi + x4.w);
    ((float4*)out)[i] = o;
}

// ---------------- launch ----------------
extern "C" void kernel_launch(void* const* d_in, const int* in_sizes, int n_in,
                              void* d_out, int out_size) {
    const float* x     = (const float*)d_in[0];
    const float* Wt    = (const float*)d_in[1];
    const float* Wp    = (const float*)d_in[2];
    const float* Wg    = (const float*)d_in[3];
    const float* Wz    = (const float*)d_in[4];
    const float* gamma = (const float*)d_in[5];
    const float* beta  = (const float*)d_in[6];
    float* out = (float*)d_out;

    k_prep<<<512, 128>>>(Wt, Wz);
    k_att<<<dim3(32, 4, B_), 256, SMEM_BYTES>>>(x, Wp, Wg);
    k_u<<<dim3(32, 4, B_), 256, SMEM_BYTES>>>(x);
    k_stats<<<B_, CIN>>>(gamma, beta);
    k_final<<<32768, 256>>>(x, out);
}

// round 5
// speedup vs baseline: 1.7059x; 1.2152x over previous
#include <cuda_runtime.h>
#include <cuda_fp16.h>
#include <cstdint>
#include <cstddef>

// Problem constants
#define B_   16
#define CIN  512
#define HW   4096
#define G_   8
#define EPSG 1e-5f
#define STILES 32           // HW / 128

// Fused GEMM: M=256 (128 Wcomb + 64 Wp + 64 Wg), N=128, K=512, 4-stage cp.async
#define AS_LD 20            // A smem row stride (words): 16 data + 4 pad
#define BS_LD 68            // B smem k-row stride (words): 64 data + 4 pad
#define A_STG 20480         // 256*20*4 bytes
#define B_STG 8704          // 32*68*4 bytes
#define B_OFF 81920         // 4*A_STG
#define SMEM_TOTAL (B_OFF + 4*B_STG)   // 116736
#define DMP_LD 66           // g-dump row stride (floats) — even => float2-aligned

// ---------------- device scratch ----------------
__device__ __half g_A16[4*256*CIN];              // fused weights, fp16
__device__ __half g_x16[(size_t)B_*CIN*HW];      // x, fp16 (67 MB)
__device__ __half g_u[(size_t)B_*CIN*HW];        // u intermediate, fp16 (67 MB)
__device__ float  g_attp[B_*G_*STILES];
__device__ float  g_sump[B_*G_*STILES];
__device__ float  g_sumsqp[B_*G_*STILES];
__device__ float  g_scale[B_*CIN];
__device__ float  g_bias[B_*CIN];

// ---------------- PTX helpers ----------------
__device__ __forceinline__ uint32_t smem_u32(const void* p) {
    uint32_t a;
    asm("{ .reg .u64 t; cvta.to.shared.u64 t, %1; cvt.u32.u64 %0, t; }" : "=r"(a) : "l"(p));
    return a;
}
__device__ __forceinline__ void cpasync16(uint32_t dst, const void* src) {
    asm volatile("cp.async.cg.shared.global [%0], [%1], 16;" :: "r"(dst), "l"(src) : "memory");
}
#define CP_COMMIT()  asm volatile("cp.async.commit_group;" ::: "memory")
#define CP_WAIT(n)   asm volatile("cp.async.wait_group %0;" :: "n"(n) : "memory")

__device__ __forceinline__ void ldsm4(unsigned* r, uint32_t a) {
    asm volatile("ldmatrix.sync.aligned.m8n8.x4.shared.b16 {%0,%1,%2,%3}, [%4];"
        : "=r"(r[0]), "=r"(r[1]), "=r"(r[2]), "=r"(r[3]) : "r"(a));
}
__device__ __forceinline__ void ldsm4t(unsigned* r, uint32_t a) {
    asm volatile("ldmatrix.sync.aligned.m8n8.x4.trans.shared.b16 {%0,%1,%2,%3}, [%4];"
        : "=r"(r[0]), "=r"(r[1]), "=r"(r[2]), "=r"(r[3]) : "r"(a));
}
__device__ __forceinline__ void mma16(float* c, const unsigned* a, const unsigned* b) {
    asm volatile(
        "mma.sync.aligned.m16n8k16.row.col.f32.f16.f16.f32 "
        "{%0,%1,%2,%3}, {%4,%5,%6,%7}, {%8,%9}, {%0,%1,%2,%3};\n"
        : "+f"(c[0]), "+f"(c[1]), "+f"(c[2]), "+f"(c[3])
        : "r"(a[0]), "r"(a[1]), "r"(a[2]), "r"(a[3]), "r"(b[0]), "r"(b[1]));
}
__device__ __forceinline__ float wred(float v) {
#pragma unroll
    for (int o = 16; o; o >>= 1) v += __shfl_down_sync(0xffffffffu, v, o);
    return v;
}

// ---------------- K1: build fused fp16 A (Wcomb | Wp | Wg) ----------------
__global__ void k_prepA(const float* __restrict__ Wt, const float* __restrict__ Wp,
                        const float* __restrict__ Wg, const float* __restrict__ Wz) {
    const int r = blockIdx.x;          // 0..255 (row within yb block)
    const int yb = blockIdx.y;         // 0..3
    __half* dst = g_A16 + ((size_t)yb*256 + r)*CIN;
    if (r < 128) {
        int R = yb*128 + r;            // Wcomb row
        int g = R >> 6, o = R & 63;
        __shared__ float wz[32];
        if (threadIdx.x < 32) wz[threadIdx.x] = Wz[(size_t)(g*64 + o)*32 + threadIdx.x];
        __syncthreads();
        for (int i = threadIdx.x; i < CIN; i += blockDim.x) {
            float a = 0.f;
#pragma unroll 8
            for (int c = 0; c < 32; c++)
                a += wz[c] * Wt[(size_t)(g*32 + c)*CIN + i];
            dst[i] = __float2half(a);
        }
    } else {
        const float* src = (r < 192) ? Wp + (size_t)(yb*64 + r - 128)*CIN
                                     : Wg + (size_t)(yb*64 + r - 192)*CIN;
        for (int i = threadIdx.x; i < CIN; i += blockDim.x)
            dst[i] = __float2half(src[i]);
    }
}

// ---------------- K2: x -> fp16 ----------------
__global__ void k_prepX(const float* __restrict__ x) {
    size_t i = (size_t)blockIdx.x * blockDim.x + threadIdx.x;   // float4 index
    float4 v = ((const float4*)x)[i];
    __half2* d = (__half2*)g_x16;
    d[2*i]     = __floats2half2_rn(v.x, v.y);
    d[2*i + 1] = __floats2half2_rn(v.z, v.w);
}

// ---------------- K3: fused GEMM (u + att) ----------------
// C[256,128] = A16[yb][256,512] @ x16[b][512, stile*128 .. +128]
__global__ void __launch_bounds__(256, 1)
k_gemm() {
    extern __shared__ char smem[];
    const uint32_t sb = smem_u32(smem);
    __shared__ float rbuf[16];

    const int tid  = threadIdx.x;
    const int lane = tid & 31, warp = tid >> 5;
    const int wm = warp >> 1, wn = warp & 1;     // 4(m) x 2(n) warps; warp tile 64m x 64n
    const int stile = blockIdx.x, yb = blockIdx.y, b = blockIdx.z;
    const int scol0 = stile * 128;

    // cp.async source pointers
    const int am = (tid >> 2), ac4 = tid & 3;    // A chunks: m = am + p*64
    const int bk = (tid >> 4), bn16 = tid & 15;  // B chunks: k = bk + p*16
    const __half* asrc[4];
#pragma unroll
    for (int p = 0; p < 4; p++)
        asrc[p] = g_A16 + ((size_t)yb*256 + am + p*64)*CIN + ac4*8;
    const __half* bsrc[2];
#pragma unroll
    for (int p = 0; p < 2; p++)
        bsrc[p] = g_x16 + ((size_t)b*CIN + bk + p*16)*HW + scol0 + bn16*8;
    const uint32_t adst = sb + am*80 + ac4*16;             // within A stage
    const uint32_t bdst = sb + B_OFF + bk*272 + bn16*16;   // within B stage

    auto issue = [&](int s) {
        if (s < 16) {
            const int i = s & 3;
#pragma unroll
            for (int p = 0; p < 4; p++)
                cpasync16(adst + i*A_STG + p*64*80, asrc[p] + s*32);
#pragma unroll
            for (int p = 0; p < 2; p++)
                cpasync16(bdst + i*B_STG + p*16*272, bsrc[p] + (size_t)s*32*HW);
        }
        CP_COMMIT();
    };

    // ldmatrix lane addressing
    const int mat = lane >> 3, rowin = lane & 7;
    const int a_row = wm*64 + (mat & 1)*8 + rowin;     // + mt*16
    const int a_kw  = (lane >> 4) * 4;                  // + ks*8
    const int b_k   = (mat & 1)*8 + rowin;              // + ks*16
    const int b_w   = (lane >> 4) * 4;                  // + wn*32 + ng*8

    float acc[4][8][4];
#pragma unroll
    for (int mt = 0; mt < 4; mt++)
#pragma unroll
        for (int nt = 0; nt < 8; nt++)
#pragma unroll
            for (int i = 0; i < 4; i++) acc[mt][nt][i] = 0.f;

    issue(0);
    issue(1);

    for (int s = 0; s < 16; s++) {
        issue(s + 2);
        CP_WAIT(2);
        __syncthreads();
        const uint32_t abuf = sb + (s & 3)*A_STG;
        const uint32_t bbuf = sb + B_OFF + (s & 3)*B_STG;
#pragma unroll
        for (int ks = 0; ks < 2; ks++) {
            unsigned af[4][4], bf[4][4];
#pragma unroll
            for (int mt = 0; mt < 4; mt++)
                ldsm4(af[mt], abuf + ((a_row + mt*16)*AS_LD + ks*8 + a_kw)*4);
#pragma unroll
            for (int ng = 0; ng < 4; ng++)
                ldsm4t(bf[ng], bbuf + ((ks*16 + b_k)*BS_LD + wn*32 + ng*8 + b_w)*4);
#pragma unroll
            for (int mt = 0; mt < 4; mt++)
#pragma unroll
                for (int ng = 0; ng < 4; ng++) {
                    mma16(acc[mt][2*ng],     af[mt], &bf[ng][0]);
                    mma16(acc[mt][2*ng + 1], af[mt], &bf[ng][2]);
                }
        }
        __syncthreads();   // protect buf (s+2)&3 written next iter vs laggard readers
    }
    CP_WAIT(0);
    __syncthreads();

    const int lr = lane >> 2, lc2 = (lane & 3)*2;

    if (wm < 2) {
        // ---- u rows: channels yb*128 + wm*64 + ... ; GN group = yb*2 + wm ----
        float s1 = 0.f, s2 = 0.f;
        const size_t ub = ((size_t)b*CIN + yb*128 + wm*64)*HW + scol0 + wn*64;
#pragma unroll
        for (int mt = 0; mt < 4; mt++)
#pragma unroll
            for (int nt = 0; nt < 8; nt++)
#pragma unroll
                for (int i2 = 0; i2 < 2; i2++) {
                    float v0 = acc[mt][nt][i2*2], v1 = acc[mt][nt][i2*2 + 1];
                    int r = mt*16 + lr + i2*8;
                    int c = nt*8 + lc2;
                    *(__half2*)&g_u[ub + (size_t)r*HW + c] = __floats2half2_rn(v0, v1);
                    s1 += v0 + v1;
                    s2 += v0*v0 + v1*v1;
                }
        s1 = wred(s1); s2 = wred(s2);
        if (lane == 0) { rbuf[wm*2 + wn] = s1; rbuf[4 + wm*2 + wn] = s2; }
    } else if (wm == 3) {
        // ---- g rows: dump to smem for the p warps ----
        float* dmp = (float*)(smem) + wn*64*DMP_LD;   // 64 x DMP_LD floats
#pragma unroll
        for (int mt = 0; mt < 4; mt++)
#pragma unroll
            for (int nt = 0; nt < 8; nt++)
#pragma unroll
                for (int i2 = 0; i2 < 2; i2++) {
                    int r = mt*16 + lr + i2*8;
                    int c = nt*8 + lc2;
                    *(float2*)&dmp[r*DMP_LD + c] = make_float2(acc[mt][nt][i2*2], acc[mt][nt][i2*2+1]);
                }
    }
    __syncthreads();
    if (wm == 2) {
        // ---- p rows: att = sum p*g ----
        const float* dmp = (const float*)(smem) + wn*64*DMP_LD;
        float pg0 = 0.f, pg1 = 0.f;
#pragma unroll
        for (int mt = 0; mt < 4; mt++) {
            float local = 0.f;
#pragma unroll
            for (int nt = 0; nt < 8; nt++)
#pragma unroll
                for (int i2 = 0; i2 < 2; i2++) {
                    int r = mt*16 + lr + i2*8;
                    int c = nt*8 + lc2;
                    local += acc[mt][nt][i2*2] * dmp[r*DMP_LD + c]
                           + acc[mt][nt][i2*2 + 1] * dmp[r*DMP_LD + c + 1];
                }
            if (mt < 2) pg0 += local; else pg1 += local;
        }
        pg0 = wred(pg0); pg1 = wred(pg1);
        if (lane == 0) { rbuf[8 + wn*2] = pg0; rbuf[8 + wn*2 + 1] = pg1; }
    }
    __syncthreads();
    if (tid < 2) {
        int g = yb*2 + tid;
        g_sump[((b*G_ + g)*STILES) + stile]   = rbuf[tid*2] + rbuf[tid*2 + 1];
        g_sumsqp[((b*G_ + g)*STILES) + stile] = rbuf[4 + tid*2] + rbuf[4 + tid*2 + 1];
        g_attp[((b*G_ + g)*STILES) + stile]   = rbuf[8 + tid] + rbuf[8 + tid + 2];
    }
}

// ---------------- K4: fold att + GN into per-(b,c) scale/bias ----------------
__global__ void k_stats(const float* __restrict__ gamma, const float* __restrict__ beta) {
    int b = blockIdx.x, c = threadIdx.x;
    __shared__ float sS[8], sMu[8];
    if (c < 8) {
        float att = 0.f, sm = 0.f, sq = 0.f;
#pragma unroll
        for (int t = 0; t < STILES; t++) {
            att += g_attp[(b*G_ + c)*STILES + t];
            sm  += g_sump[(b*G_ + c)*STILES + t];
            sq  += g_sumsqp[(b*G_ + c)*STILES + t];
        }
        const float n = 64.0f * 4096.0f;
        float mu  = sm / n;
        float var = fmaxf(sq / n - mu*mu, 0.f);
        float rstd = rsqrtf(att*att*var + EPSG);   // var_z = att^2 * var_u
        sS[c]  = att * rstd;
        sMu[c] = mu;
    }
    __syncthreads();
    int g = c >> 6;
    float S = sS[g], mu = sMu[g];
    g_scale[b*CIN + c] = S * gamma[c];
    g_bias[b*CIN + c]  = beta[c] - S * mu * gamma[c];
}

// ---------------- K5: out = scale*u + bias + x ----------------
__global__ void k_final(const float* __restrict__ x, float* __restrict__ out) {
    size_t i = (size_t)blockIdx.x * blockDim.x + threadIdx.x;   // float4 index
    size_t e = i << 2;
    int b = (int)(e >> 21);
    int c = (int)((e >> 12) & 511);
    float sc = g_scale[b*CIN + c];
    float bi = g_bias[b*CIN + c];
    const __half2* up = (const __half2*)g_u;
    float2 u0 = __half22float2(up[2*i]);
    float2 u1 = __half22float2(up[2*i + 1]);
    float4 x4 = ((const float4*)x)[i];
    float4 o;
    o.x = fmaf(sc, u0.x, bi + x4.x);
    o.y = fmaf(sc, u0.y, bi + x4.y);
    o.z = fmaf(sc, u1.x, bi + x4.z);
    o.w = fmaf(sc, u1.y, bi + x4.w);
    ((float4*)out)[i] = o;
}

// ---------------- launch ----------------
extern "C" void kernel_launch(void* const* d_in, const int* in_sizes, int n_in,
                              void* d_out, int out_size) {
    const float* x     = (const float*)d_in[0];
    const float* Wt    = (const float*)d_in[1];
    const float* Wp    = (const float*)d_in[2];
    const float* Wg    = (const float*)d_in[3];
    const float* Wz    = (const float*)d_in[4];
    const float* gamma = (const float*)d_in[5];
    const float* beta  = (const float*)d_in[6];
    float* out = (float*)d_out;

    cudaFuncSetAttribute(k_gemm, cudaFuncAttributeMaxDynamicSharedMemorySize, SMEM_TOTAL);

    k_prepA<<<dim3(256, 4), 256>>>(Wt, Wp, Wg, Wz);
    k_prepX<<<32768, 256>>>(x);
    k_gemm<<<dim3(STILES, 4, B_), 256, SMEM_TOTAL>>>();
    k_stats<<<B_, CIN>>>(gamma, beta);
    k_final<<<32768, 256>>>(x, out);
}